// round 14
// baseline (speedup 1.0000x reference)
#include <cuda_runtime.h>
#include <cuda_fp16.h>
#include <math.h>
#include <cstdint>

#define NV 117000
#define NE 468000
#define EMB 300
#define IN_DIM 768
#define BATCH 4096
#define HID 500
#define FCK (EMB + IN_DIM)   // 1068
#define NBLK_SCAN ((NV + 1023) / 1024)   // 115
#define AP 320               // padded fp16 stride for GCN activations/weights
#define FCP 1088             // padded fc width
#define HP 512               // padded hidden width
#define BNROWS 640           // padded N-rows for transposed MLP weights
#define GEN 1                // constant generation stamp (mark-only flags)

// ---------------- device scratch (allocation-free, zero-initialized) -------
__device__ int   g_cnt[NV];
__device__ int   g_rowstart[NV + 1];
__device__ int   g_tot[256];
__device__ int   g_cursor[NV];
__device__ int   g_scol[NE];
__device__ float g_sval[NE];
__device__ float g_h2[BATCH * HID];
__device__ float g_part[BATCH * HID];    // MLP-G1 part-A partial accumulator
// frontier machinery
__device__ int   g_fnode[NV];
__device__ int   g_f1[NV];       // S1 (1-hop)
__device__ int   g_f2[NV];       // S2 (2-hop)
__device__ int   g_list1[NV];    // compacted S1
__device__ int   g_list3[NV];    // compacted S2
__device__ int   g_n1;
__device__ int   g_n3;
// fp16 buffers (pads stay statically zero — never written with nonzero)
__device__ __half g_act[(size_t)NV * AP];           // H0 f16 / H1 (S1 rows)
__device__ __half g_x16[(size_t)NV * AP];           // Y = A*H0 (S1) / Z dense
__device__ __half g_w1t[AP * AP];
__device__ __half g_w2t[AP * AP];
__device__ __half g_fcf16[(size_t)BATCH * FCP];
__device__ __half g_wat[(size_t)BNROWS * FCP];
__device__ __half g_wbt[(size_t)BNROWS * HP];
__device__ __half g_h1f16[(size_t)BATCH * HP];

// ================= helpers =================
__device__ __forceinline__ void mma16816(float* c, const uint32_t* a, const uint32_t* b) {
    asm volatile(
        "mma.sync.aligned.m16n8k16.row.col.f32.f16.f16.f32 "
        "{%0,%1,%2,%3}, {%4,%5,%6,%7}, {%8,%9}, {%0,%1,%2,%3};"
        : "+f"(c[0]), "+f"(c[1]), "+f"(c[2]), "+f"(c[3])
        : "r"(a[0]), "r"(a[1]), "r"(a[2]), "r"(a[3]),
          "r"(b[0]), "r"(b[1]));
}

__device__ __forceinline__ uint32_t cvta_shared_u32(const void* p) {
    uint32_t a;
    asm("{ .reg .u64 t; cvta.to.shared.u64 t, %1; cvt.u32.u64 %0, t; }"
        : "=r"(a) : "l"(p));
    return a;
}

__device__ __forceinline__ void cp_async16(uint32_t dst, const void* src) {
    asm volatile("cp.async.ca.shared.global [%0], [%1], 16;" :: "r"(dst), "l"(src));
}
__device__ __forceinline__ void cp_commit() {
    asm volatile("cp.async.commit_group;");
}
__device__ __forceinline__ void cp_wait0() {
    asm volatile("cp.async.wait_group 0;");
}

// ================= prep kernels =================
__global__ void pre_act_list_kernel(const float* __restrict__ X,
                                    const int* __restrict__ rowlist,
                                    const int* __restrict__ pcount) {
    int idx = blockIdx.x * blockDim.x + threadIdx.x;
    int cnt = *pcount;
    int i = idx / 75;
    if (i >= cnt) return;
    int q = idx - i * 75;
    int r = rowlist[i];
    float4 v = reinterpret_cast<const float4*>(X)[(size_t)r * 75 + q];
    __half2 p0 = __floats2half2_rn(v.x, v.y);
    __half2 p1 = __floats2half2_rn(v.z, v.w);
    uint2 pk = make_uint2(*reinterpret_cast<uint32_t*>(&p0),
                          *reinterpret_cast<uint32_t*>(&p1));
    *reinterpret_cast<uint2*>(&g_act[(size_t)r * AP + q * 4]) = pk;
}

__global__ void pre_wT_kernel(const float* __restrict__ W, int K, int N, int ldo,
                              __half* __restrict__ t16) {
    int idx = blockIdx.x * blockDim.x + threadIdx.x;
    if (idx >= K * N) return;
    int k = idx / N;
    int n = idx - k * N;
    t16[(size_t)n * ldo + k] = __float2half_rn(W[idx]);
}

// input fp32 [BATCH, IN_DIM] -> fc columns [EMB, EMB+IN_DIM) as fp16
__global__ void pre_input_f16_kernel(const float* __restrict__ input) {
    int idx = blockIdx.x * blockDim.x + threadIdx.x;
    if (idx >= BATCH * 192) return;
    int b = idx / 192;
    int q = idx - b * 192;
    float4 v = reinterpret_cast<const float4*>(input)[(size_t)b * 192 + q];
    __half2 p0 = __floats2half2_rn(v.x, v.y);
    __half2 p1 = __floats2half2_rn(v.z, v.w);
    uint2 pk = make_uint2(*reinterpret_cast<uint32_t*>(&p0),
                          *reinterpret_cast<uint32_t*>(&p1));
    *reinterpret_cast<uint2*>(&g_fcf16[(size_t)b * FCP + EMB + q * 4]) = pk;
}

// ================= frontier kernels =================
__global__ void mark_node_kernel(const int* __restrict__ node) {
    int i = blockIdx.x * blockDim.x + threadIdx.x;
    if (i == 0) { g_n1 = 0; g_n3 = 0; }
    if (i < BATCH) g_fnode[node[i]] = GEN;
}

__global__ void mark_1hop_kernel(const int* __restrict__ erow,
                                 const int* __restrict__ ecol) {
    int e = blockIdx.x * blockDim.x + threadIdx.x;
    if (e >= NE) return;
    if (g_fnode[erow[e]] == GEN) g_f1[ecol[e]] = GEN;
}

__global__ void mark_2hop_kernel(const int* __restrict__ erow,
                                 const int* __restrict__ ecol) {
    int e = blockIdx.x * blockDim.x + threadIdx.x;
    if (e >= NE) return;
    if (g_f1[erow[e]] == GEN) g_f2[ecol[e]] = GEN;
}

__global__ void compact_both_kernel() {
    int i = blockIdx.x * blockDim.x + threadIdx.x;
    if (i >= NV) return;
    if (g_f2[i] == GEN) {
        int p = atomicAdd(&g_n3, 1);
        g_list3[p] = i;
    }
    if (g_f1[i] == GEN) {
        int p = atomicAdd(&g_n1, 1);
        g_list1[p] = i;
    }
}

// ================= pipelined fp16 tensor-core GEMM ==========================
// C[M,N] = A[rows, K] @ B[K,N]; optional rowlist/pcount select A rows.
// bias added when non-null.
// mode 0: fp32   1: sigmoid fp32   2: sigmoid fp16   3: plain fp16
// mode 4: acc += C partial (fp32 ldc), then sigmoid -> fp16 (o16, ldo)
#define GS_ABUF 10240
#define GS_BBUF 12800
#define GS_BOFF (2 * GS_ABUF)                  // 20480
#define GS_TOTAL (GS_BOFF + 2 * GS_BBUF)       // 46080 dynamic

__global__ void __launch_bounds__(512)
gemm_f16_kernel(const __half* __restrict__ a16, int lda,
                const __half* __restrict__ bt, int ldb,
                float* __restrict__ C, int ldc,
                __half* __restrict__ o16, int ldo,
                const float* __restrict__ bias,
                const int* __restrict__ rowlist, const int* __restrict__ pcount,
                int M, int N, int K, int mode) {
    extern __shared__ __align__(16) char sm[];
    __shared__ int rows_sm[128];

    int cnt = pcount ? *pcount : M;
    int bm = blockIdx.y * 128;
    if (bm >= cnt) return;

    int tid = threadIdx.x;
    if (tid < 128) {
        int gi = bm + tid;
        if (gi > cnt - 1) gi = cnt - 1;
        rows_sm[tid] = rowlist ? rowlist[gi] : gi;
    }
    __syncthreads();

    int w = tid >> 5;
    int lane = tid & 31;
    int g = lane >> 2;
    int t2 = (lane & 3) * 2;

    int bn = blockIdx.x * 160;
    int m0 = (w & 3) * 32;
    int n0 = (w >> 2) * 40;
    int nch = K >> 5;

    float acc[2][5][4];
#pragma unroll
    for (int i = 0; i < 2; i++)
#pragma unroll
        for (int j = 0; j < 5; j++)
#pragma unroll
            for (int q = 0; q < 4; q++) acc[i][j][q] = 0.0f;

    auto prefetch = [&](int ch, int buf) {
        int k0 = ch * 32;
        {
            int r = tid >> 2;
            int c = tid & 3;
            size_t so = (size_t)rows_sm[r] * lda + k0 + c * 8;
            uint32_t d = cvta_shared_u32(sm + buf * GS_ABUF + (r * 40 + c * 8) * 2);
            cp_async16(d, a16 + so);
        }
#pragma unroll
        for (int it = 0; it < 2; it++) {
            int idx = tid + it * 512;
            if (idx < 640) {
                int r = idx >> 2;
                int c = idx & 3;
                size_t so = (size_t)(bn + r) * ldb + k0 + c * 8;
                uint32_t d = cvta_shared_u32(sm + GS_BOFF + buf * GS_BBUF +
                                             (r * 40 + c * 8) * 2);
                cp_async16(d, bt + so);
            }
        }
    };

    prefetch(0, 0);
    cp_commit();

    for (int ch = 0; ch < nch; ch++) {
        int buf = ch & 1;
        cp_wait0();
        __syncthreads();
        if (ch < nch - 1) {
            prefetch(ch + 1, buf ^ 1);
            cp_commit();
        }
        const __half* Af = reinterpret_cast<const __half*>(sm + buf * GS_ABUF);
        const __half* Bf = reinterpret_cast<const __half*>(sm + GS_BOFF + buf * GS_BBUF);

#pragma unroll
        for (int kc = 0; kc < 32; kc += 16) {
            uint32_t af[2][4];
#pragma unroll
            for (int i = 0; i < 2; i++) {
                int rm = m0 + i * 16;
                af[i][0] = *reinterpret_cast<const uint32_t*>(&Af[(rm + g)     * 40 + kc + t2]);
                af[i][1] = *reinterpret_cast<const uint32_t*>(&Af[(rm + g + 8) * 40 + kc + t2]);
                af[i][2] = *reinterpret_cast<const uint32_t*>(&Af[(rm + g)     * 40 + kc + t2 + 8]);
                af[i][3] = *reinterpret_cast<const uint32_t*>(&Af[(rm + g + 8) * 40 + kc + t2 + 8]);
            }
#pragma unroll
            for (int j = 0; j < 5; j++) {
                int rn = n0 + j * 8;
                uint32_t bf[2];
                bf[0] = *reinterpret_cast<const uint32_t*>(&Bf[(rn + g) * 40 + kc + t2]);
                bf[1] = *reinterpret_cast<const uint32_t*>(&Bf[(rn + g) * 40 + kc + t2 + 8]);
#pragma unroll
                for (int i = 0; i < 2; i++)
                    mma16816(acc[i][j], af[i], bf);
            }
        }
        __syncthreads();
    }

    // ---- epilogue ----
#pragma unroll
    for (int i = 0; i < 2; i++) {
#pragma unroll
        for (int j = 0; j < 5; j++) {
            int gn = bn + n0 + j * 8 + t2;
            if (gn >= N) continue;      // N even, gn even -> gn+1 safe
#pragma unroll
            for (int half = 0; half < 2; half++) {
                int gm = bm + m0 + i * 16 + g + half * 8;
                if (gm >= cnt) continue;
                int gr = rows_sm[gm - bm];
                float2 o;
                o.x = acc[i][j][half * 2 + 0];
                o.y = acc[i][j][half * 2 + 1];
                if (mode == 4) {
                    float2 p = *reinterpret_cast<const float2*>(C + (size_t)gr * ldc + gn);
                    o.x += p.x;
                    o.y += p.y;
                }
                if (bias) {
                    o.x += bias[gn];
                    o.y += bias[gn + 1];
                }
                if (mode == 1 || mode == 2 || mode == 4) {
                    o.x = 1.0f / (1.0f + __expf(-o.x));
                    o.y = 1.0f / (1.0f + __expf(-o.y));
                }
                if (mode >= 2) {
                    __half2 hv = __floats2half2_rn(o.x, o.y);
                    *reinterpret_cast<uint32_t*>(&o16[(size_t)gr * ldo + gn]) =
                        *reinterpret_cast<uint32_t*>(&hv);
                } else {
                    *reinterpret_cast<float2*>(C + (size_t)gr * ldc + gn) = o;
                }
            }
        }
    }
}

// ================= graph preprocessing (shortened chain) =====================
__global__ void zero_both_kernel() {
    int i = blockIdx.x * blockDim.x + threadIdx.x;
    if (i < NV) { g_cnt[i] = 0; g_cursor[i] = 0; }
}

__global__ void count_kernel(const int* __restrict__ erow) {
    int e = blockIdx.x * blockDim.x + threadIdx.x;
    if (e < NE) atomicAdd(&g_cnt[erow[e]], 1);
}

// shuffle-based two-level block scan over 1024 elems (2 syncthreads)
__global__ void scanA_kernel() {
    __shared__ int ws[32];
    int i = blockIdx.x * 1024 + threadIdx.x;
    int lane = threadIdx.x & 31;
    int wid = threadIdx.x >> 5;
    int v = (i < NV) ? g_cnt[i] : 0;
    int x = v;
#pragma unroll
    for (int o = 1; o < 32; o <<= 1) {
        int t = __shfl_up_sync(0xFFFFFFFFu, x, o);
        if (lane >= o) x += t;
    }
    if (lane == 31) ws[wid] = x;
    __syncthreads();
    if (wid == 0) {
        int y = ws[lane];
#pragma unroll
        for (int o = 1; o < 32; o <<= 1) {
            int t = __shfl_up_sync(0xFFFFFFFFu, y, o);
            if (lane >= o) y += t;
        }
        ws[lane] = y;
    }
    __syncthreads();
    int base = (wid > 0) ? ws[wid - 1] : 0;
    int incl = base + x;
    if (i < NV) g_rowstart[i] = incl - v;   // exclusive
    if (threadIdx.x == 1023) g_tot[blockIdx.x] = incl;
}

__global__ void scanB_kernel() {
    __shared__ int s[128];
    int v = (threadIdx.x < NBLK_SCAN) ? g_tot[threadIdx.x] : 0;
    s[threadIdx.x] = v;
    __syncthreads();
    for (int o = 1; o < 128; o <<= 1) {
        int t = 0;
        if (threadIdx.x >= o) t = s[threadIdx.x - o];
        __syncthreads();
        if (threadIdx.x >= o) s[threadIdx.x] += t;
        __syncthreads();
    }
    if (threadIdx.x < NBLK_SCAN) g_tot[threadIdx.x] = s[threadIdx.x] - v;
}

__global__ void scanC_kernel() {
    int i = blockIdx.x * blockDim.x + threadIdx.x;
    if (i < NV) g_rowstart[i] += g_tot[i >> 10];
    if (i == 0) g_rowstart[NV] = NE;
}

// scatter + inline normalization values (vals kernel folded in)
__global__ void scatter_kernel(const int* __restrict__ erow, const int* __restrict__ ecol) {
    int e = blockIdx.x * blockDim.x + threadIdx.x;
    if (e >= NE) return;
    int r = erow[e];
    int c = ecol[e];
    int pos = g_rowstart[r] + atomicAdd(&g_cursor[r], 1);
    g_scol[pos] = c;
    int dc = g_cnt[c];
    float val = 0.0f;
    if (dc > 0)
        val = rsqrtf((float)g_cnt[r]) * rsqrtf((float)dc);   // cnt[r] >= 1 here
    g_sval[pos] = val;
}

// ================= fp16 pull SpMM (LINEAR — no sigmoid) =====================
__device__ __forceinline__ void fma8(float* acc, uint4 t, float v) {
    __half2 p;
    float2 f;
    *reinterpret_cast<uint32_t*>(&p) = t.x; f = __half22float2(p);
    acc[0] += v * f.x; acc[1] += v * f.y;
    *reinterpret_cast<uint32_t*>(&p) = t.y; f = __half22float2(p);
    acc[2] += v * f.x; acc[3] += v * f.y;
    *reinterpret_cast<uint32_t*>(&p) = t.z; f = __half22float2(p);
    acc[4] += v * f.x; acc[5] += v * f.y;
    *reinterpret_cast<uint32_t*>(&p) = t.w; f = __half22float2(p);
    acc[6] += v * f.x; acc[7] += v * f.y;
}

__device__ __forceinline__ void spmm_accum(const __half* __restrict__ X,
                                           int row, int lane, bool lo8,
                                           float* a, float* b) {
    int s = g_rowstart[row];
    int e = g_rowstart[row + 1];
    int j = s;
    for (; j + 1 < e; j += 2) {
        int c0 = g_scol[j];
        float v0 = g_sval[j];
        int c1 = g_scol[j + 1];
        float v1 = g_sval[j + 1];
        const uint4* x0 = reinterpret_cast<const uint4*>(X + (size_t)c0 * AP);
        const uint4* x1 = reinterpret_cast<const uint4*>(X + (size_t)c1 * AP);
        uint4 t0 = x0[lane];
        uint4 t1 = x1[lane];
        fma8(a, t0, v0);
        fma8(a, t1, v1);
        if (lo8) {
            uint4 s0 = x0[32 + lane];
            uint4 s1 = x1[32 + lane];
            fma8(b, s0, v0);
            fma8(b, s1, v1);
        }
    }
    if (j < e) {
        int c = g_scol[j];
        float v = g_sval[j];
        const uint4* x4 = reinterpret_cast<const uint4*>(X + (size_t)c * AP);
        fma8(a, x4[lane], v);
        if (lo8) fma8(b, x4[32 + lane], v);
    }
}

__device__ __forceinline__ void spmm_store_lin(__half* __restrict__ O, int orow,
                                               int lane, bool lo8,
                                               const float* a, const float* b) {
    __half2 h0 = __floats2half2_rn(a[0], a[1]);
    __half2 h1 = __floats2half2_rn(a[2], a[3]);
    __half2 h2 = __floats2half2_rn(a[4], a[5]);
    __half2 h3 = __floats2half2_rn(a[6], a[7]);
    uint4 pk;
    pk.x = *reinterpret_cast<uint32_t*>(&h0);
    pk.y = *reinterpret_cast<uint32_t*>(&h1);
    pk.z = *reinterpret_cast<uint32_t*>(&h2);
    pk.w = *reinterpret_cast<uint32_t*>(&h3);
    __stcs(reinterpret_cast<uint4*>(O + (size_t)orow * AP) + lane, pk);
    if (lo8) {
        h0 = __floats2half2_rn(b[0], b[1]);
        h1 = __floats2half2_rn(b[2], b[3]);
        h2 = __floats2half2_rn(b[4], b[5]);
        h3 = __floats2half2_rn(b[6], b[7]);
        pk.x = *reinterpret_cast<uint32_t*>(&h0);
        pk.y = *reinterpret_cast<uint32_t*>(&h1);
        pk.z = *reinterpret_cast<uint32_t*>(&h2);
        pk.w = *reinterpret_cast<uint32_t*>(&h3);
        __stcs(reinterpret_cast<uint4*>(O + (size_t)orow * AP) + 32 + lane, pk);
    }
}

__global__ void spmm_sc_kernel(const __half* __restrict__ X, __half* __restrict__ O,
                               const int* __restrict__ rowlist,
                               const int* __restrict__ pcount) {
    int widx = (blockIdx.x * blockDim.x + threadIdx.x) >> 5;
    int lane = threadIdx.x & 31;
    int cnt = *pcount;
    if (widx >= cnt) return;
    int row = rowlist[widx];
    bool lo8 = lane < 8;
    float a[8] = {0,0,0,0,0,0,0,0};
    float b[8] = {0,0,0,0,0,0,0,0};
    spmm_accum(X, row, lane, lo8, a, b);
    spmm_store_lin(O, row, lane, lo8, a, b);
}

__global__ void spmm_dn_kernel(const __half* __restrict__ X, __half* __restrict__ O,
                               const int* __restrict__ node) {
    int b = (blockIdx.x * blockDim.x + threadIdx.x) >> 5;
    int lane = threadIdx.x & 31;
    if (b >= BATCH) return;
    int row = node[b];
    bool lo8 = lane < 8;
    float a[8] = {0,0,0,0,0,0,0,0};
    float bb[8] = {0,0,0,0,0,0,0,0};
    spmm_accum(X, row, lane, lo8, a, bb);
    spmm_store_lin(O, b, lane, lo8, a, bb);
}

// final layer
__global__ void final_kernel(const float* __restrict__ h,
                             const float* __restrict__ Wc,
                             const float* __restrict__ bc,
                             float* __restrict__ out) {
    int warp = (blockIdx.x * blockDim.x + threadIdx.x) >> 5;
    int lane = threadIdx.x & 31;
    if (warp >= BATCH) return;
    const float* hr = h + (size_t)warp * HID;
    float a0 = 0.f, a1 = 0.f;
    for (int k = lane; k < HID; k += 32) {
        float hv = hr[k];
        a0 += hv * Wc[k * 2 + 0];
        a1 += hv * Wc[k * 2 + 1];
    }
#pragma unroll
    for (int o = 16; o > 0; o >>= 1) {
        a0 += __shfl_down_sync(0xFFFFFFFFu, a0, o);
        a1 += __shfl_down_sync(0xFFFFFFFFu, a1, o);
    }
    if (lane == 0) {
        out[warp * 2 + 0] = a0 + bc[0];
        out[warp * 2 + 1] = a1 + bc[1];
    }
}

// ================= host launch =================
extern "C" void kernel_launch(void* const* d_in, const int* in_sizes, int n_in,
                              void* d_out, int out_size) {
    const float* input = (const float*)d_in[0];
    const int*   node  = (const int*)d_in[1];
    const int*   erow  = (const int*)d_in[2];
    const int*   ecol  = (const int*)d_in[3];
    const float* H0    = (const float*)d_in[4];
    const float* W1    = (const float*)d_in[5];
    const float* W2    = (const float*)d_in[6];
    const float* Wa    = (const float*)d_in[7];
    const float* ba    = (const float*)d_in[8];
    const float* Wb    = (const float*)d_in[9];
    const float* bb    = (const float*)d_in[10];
    const float* Wc    = (const float*)d_in[11];
    const float* bc    = (const float*)d_in[12];
    float*       out   = (float*)d_out;

    void *p_h2, *p_part;
    void *p_act, *p_x16, *p_w1t, *p_w2t, *p_fcf16, *p_wat, *p_wbt, *p_h1f16;
    void *p_list1, *p_list3, *p_n1, *p_n3;
    cudaGetSymbolAddress(&p_h2,     g_h2);
    cudaGetSymbolAddress(&p_part,   g_part);
    cudaGetSymbolAddress(&p_act,    g_act);
    cudaGetSymbolAddress(&p_x16,    g_x16);
    cudaGetSymbolAddress(&p_w1t,    g_w1t);
    cudaGetSymbolAddress(&p_w2t,    g_w2t);
    cudaGetSymbolAddress(&p_fcf16,  g_fcf16);
    cudaGetSymbolAddress(&p_wat,    g_wat);
    cudaGetSymbolAddress(&p_wbt,    g_wbt);
    cudaGetSymbolAddress(&p_h1f16,  g_h1f16);
    cudaGetSymbolAddress(&p_list1,  g_list1);
    cudaGetSymbolAddress(&p_list3,  g_list3);
    cudaGetSymbolAddress(&p_n1,     g_n1);
    cudaGetSymbolAddress(&p_n3,     g_n3);

    float* h2   = (float*)p_h2;
    float* part = (float*)p_part;

    cudaFuncSetAttribute(gemm_f16_kernel,
                         cudaFuncAttributeMaxDynamicSharedMemorySize, GS_TOTAL);

    static cudaStream_t s2 = nullptr, s3 = nullptr;
    static cudaEvent_t evF = nullptr, evFront = nullptr, evCsr = nullptr;
    if (!s2) {
        cudaStreamCreateWithFlags(&s2, cudaStreamNonBlocking);
        cudaStreamCreateWithFlags(&s3, cudaStreamNonBlocking);
        cudaEventCreateWithFlags(&evF, cudaEventDisableTiming);
        cudaEventCreateWithFlags(&evFront, cudaEventDisableTiming);
        cudaEventCreateWithFlags(&evCsr, cudaEventDisableTiming);
    }

    const int TPB = 256;
    const int nvBlocks = (NV + TPB - 1) / TPB;
    const int neBlocks = (NE + TPB - 1) / TPB;

    cudaEventRecord(evF, 0);

    // ---- s2: frontier construction ----
    cudaStreamWaitEvent(s2, evF, 0);
    mark_node_kernel<<<(BATCH + TPB - 1) / TPB, TPB, 0, s2>>>(node);
    mark_1hop_kernel<<<neBlocks, TPB, 0, s2>>>(erow, ecol);
    mark_2hop_kernel<<<neBlocks, TPB, 0, s2>>>(erow, ecol);
    compact_both_kernel<<<nvBlocks, TPB, 0, s2>>>();
    cudaEventRecord(evFront, s2);

    // ---- s3: shortened CSR build ----
    cudaStreamWaitEvent(s3, evF, 0);
    zero_both_kernel<<<nvBlocks, TPB, 0, s3>>>();
    count_kernel<<<neBlocks, TPB, 0, s3>>>(erow);
    scanA_kernel<<<NBLK_SCAN, 1024, 0, s3>>>();
    scanB_kernel<<<1, 128, 0, s3>>>();
    scanC_kernel<<<nvBlocks, TPB, 0, s3>>>();
    scatter_kernel<<<neBlocks, TPB, 0, s3>>>(erow, ecol);
    cudaEventRecord(evCsr, s3);

    // ---- main stream: weight + input conversions ----
    pre_wT_kernel<<<(EMB * EMB + TPB - 1) / TPB, TPB>>>(W1, EMB, EMB, AP, (__half*)p_w1t);
    pre_wT_kernel<<<(EMB * EMB + TPB - 1) / TPB, TPB>>>(W2, EMB, EMB, AP, (__half*)p_w2t);
    pre_wT_kernel<<<(FCK * HID + TPB - 1) / TPB, TPB>>>(Wa, FCK, HID, FCP, (__half*)p_wat);
    pre_wT_kernel<<<(HID * HID + TPB - 1) / TPB, TPB>>>(Wb, HID, HID, HP, (__half*)p_wbt);
    pre_input_f16_kernel<<<(BATCH * 192 + TPB - 1) / TPB, TPB>>>(input);

    // ---- MLP-G1 part A in main's idle window (depends only on input+Wa) ----
    // K in [320, 1088): fc cols 320..1067 (input section) + pads. Runs while
    // s2/s3 chains execute; main would otherwise idle waiting on them.
    dim3 gmlp(4, BATCH / 128);
    gemm_f16_kernel<<<gmlp, 512, GS_TOTAL>>>(
        (__half*)p_fcf16 + 320, FCP, (__half*)p_wat + 320, FCP,
        part, HID, nullptr, 0, nullptr,
        nullptr, nullptr, BATCH, HID, 768, 0);

    // ---- join frontier, then pre_act on S2 rows ----
    cudaStreamWaitEvent(0, evFront, 0);
    pre_act_list_kernel<<<(NV * 75 + TPB - 1) / TPB, TPB>>>(H0, (int*)p_list3, (int*)p_n3);

    // ---- join CSR, then Y = A*H0 on S1 rows (linear, fp16) ----
    cudaStreamWaitEvent(0, evCsr, 0);
    int spmmBlocks = (NV * 32 + TPB - 1) / TPB;
    spmm_sc_kernel<<<spmmBlocks, TPB>>>((__half*)p_act, (__half*)p_x16,
                                        (int*)p_list1, (int*)p_n1);

    // ---- H1 = sigmoid(Y @ W1) on S1 rows ----
    dim3 gbig(2, (NV + 127) / 128);
    gemm_f16_kernel<<<gbig, 512, GS_TOTAL>>>(
        (__half*)p_x16, AP, (__half*)p_w1t, AP,
        nullptr, 0, (__half*)p_act, AP, nullptr,
        (int*)p_list1, (int*)p_n1, NV, EMB, AP, 2);

    // ---- Z = A*H1 at node rows, densely packed ----
    spmm_dn_kernel<<<(BATCH * 32 + TPB - 1) / TPB, TPB>>>(
        (__half*)p_act, (__half*)p_x16, node);

    // ---- fc[:, 0:300] = sigmoid(Z @ W2) ----
    dim3 g2(2, BATCH / 128);
    gemm_f16_kernel<<<g2, 512, GS_TOTAL>>>(
        (__half*)p_x16, AP, (__half*)p_w2t, AP,
        nullptr, 0, (__half*)p_fcf16, FCP, nullptr,
        nullptr, nullptr, BATCH, EMB, AP, 2);

    // ---- MLP-G1 part B: K in [0,320), accumulate partial, bias, sigmoid ----
    gemm_f16_kernel<<<gmlp, 512, GS_TOTAL>>>(
        (__half*)p_fcf16, FCP, (__half*)p_wat, FCP,
        part, HID, (__half*)p_h1f16, HP, ba,
        nullptr, nullptr, BATCH, HID, 320, 4);

    // ---- MLP-G2 + final ----
    gemm_f16_kernel<<<gmlp, 512, GS_TOTAL>>>(
        (__half*)p_h1f16, HP, (__half*)p_wbt, HP,
        h2, HID, nullptr, 0, bb,
        nullptr, nullptr, BATCH, HID, HP, 1);

    final_kernel<<<(BATCH * 32 + TPB - 1) / TPB, TPB>>>(h2, Wc, bc, out);
}

// round 15
// speedup vs baseline: 1.0664x; 1.0664x over previous
#include <cuda_runtime.h>
#include <cuda_fp16.h>
#include <math.h>
#include <cstdint>

#define NV 117000
#define NE 468000
#define EMB 300
#define IN_DIM 768
#define BATCH 4096
#define HID 500
#define FCK (EMB + IN_DIM)   // 1068
#define NBLK_SCAN ((NV + 1023) / 1024)   // 115
#define AP 320               // padded fp16 stride for GCN activations/weights
#define FCP 1088             // padded fc width
#define HP 512               // padded hidden width
#define BNROWS 640           // padded N-rows for transposed MLP weights
#define GEN 1                // constant generation stamp (mark-only flags)

// ---------------- device scratch (allocation-free, zero-initialized) -------
__device__ int   g_cnt[NV];
__device__ int   g_rowstart[NV + 1];
__device__ int   g_tot[256];
__device__ int   g_cursor[NV];
__device__ int   g_scol[NE];
__device__ float g_sval[NE];
__device__ float g_h2[BATCH * HID];
// frontier machinery
__device__ int   g_fnode[NV];
__device__ int   g_f1[NV];       // S1 (1-hop)
__device__ int   g_f2[NV];       // S2 (2-hop)
__device__ int   g_list1[NV];    // compacted S1
__device__ int   g_list3[NV];    // compacted S2
__device__ int   g_n1;
__device__ int   g_n3;
// fp16 buffers (pads stay statically zero — never written with nonzero)
__device__ __half g_act[(size_t)NV * AP];           // H0 f16 / H1 (S1 rows)
__device__ __half g_x16[(size_t)NV * AP];           // Y = A*H0 (S1) / Z dense
__device__ __half g_w1t[AP * AP];
__device__ __half g_w2t[AP * AP];
__device__ __half g_fcf16[(size_t)BATCH * FCP];
__device__ __half g_wat[(size_t)BNROWS * FCP];
__device__ __half g_wbt[(size_t)BNROWS * HP];
__device__ __half g_h1f16[(size_t)BATCH * HP];

// ================= helpers =================
__device__ __forceinline__ void mma16816(float* c, const uint32_t* a, const uint32_t* b) {
    asm volatile(
        "mma.sync.aligned.m16n8k16.row.col.f32.f16.f16.f32 "
        "{%0,%1,%2,%3}, {%4,%5,%6,%7}, {%8,%9}, {%0,%1,%2,%3};"
        : "+f"(c[0]), "+f"(c[1]), "+f"(c[2]), "+f"(c[3])
        : "r"(a[0]), "r"(a[1]), "r"(a[2]), "r"(a[3]),
          "r"(b[0]), "r"(b[1]));
}

__device__ __forceinline__ uint32_t cvta_shared_u32(const void* p) {
    uint32_t a;
    asm("{ .reg .u64 t; cvta.to.shared.u64 t, %1; cvt.u32.u64 %0, t; }"
        : "=r"(a) : "l"(p));
    return a;
}

__device__ __forceinline__ void cp_async16(uint32_t dst, const void* src) {
    asm volatile("cp.async.ca.shared.global [%0], [%1], 16;" :: "r"(dst), "l"(src));
}
__device__ __forceinline__ void cp_commit() {
    asm volatile("cp.async.commit_group;");
}
__device__ __forceinline__ void cp_wait0() {
    asm volatile("cp.async.wait_group 0;");
}

// ================= prep kernels =================
__global__ void pre_act_list_kernel(const float* __restrict__ X,
                                    const int* __restrict__ rowlist,
                                    const int* __restrict__ pcount) {
    int idx = blockIdx.x * blockDim.x + threadIdx.x;
    int cnt = *pcount;
    int i = idx / 75;
    if (i >= cnt) return;
    int q = idx - i * 75;
    int r = rowlist[i];
    float4 v = reinterpret_cast<const float4*>(X)[(size_t)r * 75 + q];
    __half2 p0 = __floats2half2_rn(v.x, v.y);
    __half2 p1 = __floats2half2_rn(v.z, v.w);
    uint2 pk = make_uint2(*reinterpret_cast<uint32_t*>(&p0),
                          *reinterpret_cast<uint32_t*>(&p1));
    *reinterpret_cast<uint2*>(&g_act[(size_t)r * AP + q * 4]) = pk;
}

__global__ void pre_wT_kernel(const float* __restrict__ W, int K, int N, int ldo,
                              __half* __restrict__ t16) {
    int idx = blockIdx.x * blockDim.x + threadIdx.x;
    if (idx >= K * N) return;
    int k = idx / N;
    int n = idx - k * N;
    t16[(size_t)n * ldo + k] = __float2half_rn(W[idx]);
}

// input fp32 [BATCH, IN_DIM] -> fc columns [EMB, EMB+IN_DIM) as fp16
__global__ void pre_input_f16_kernel(const float* __restrict__ input) {
    int idx = blockIdx.x * blockDim.x + threadIdx.x;
    if (idx >= BATCH * 192) return;
    int b = idx / 192;
    int q = idx - b * 192;
    float4 v = reinterpret_cast<const float4*>(input)[(size_t)b * 192 + q];
    __half2 p0 = __floats2half2_rn(v.x, v.y);
    __half2 p1 = __floats2half2_rn(v.z, v.w);
    uint2 pk = make_uint2(*reinterpret_cast<uint32_t*>(&p0),
                          *reinterpret_cast<uint32_t*>(&p1));
    *reinterpret_cast<uint2*>(&g_fcf16[(size_t)b * FCP + EMB + q * 4]) = pk;
}

// ================= frontier kernels =================
__global__ void mark_node_kernel(const int* __restrict__ node) {
    int i = blockIdx.x * blockDim.x + threadIdx.x;
    if (i == 0) { g_n1 = 0; g_n3 = 0; }
    if (i < BATCH) g_fnode[node[i]] = GEN;
}

__global__ void mark_1hop_kernel(const int* __restrict__ erow,
                                 const int* __restrict__ ecol) {
    int e = blockIdx.x * blockDim.x + threadIdx.x;
    if (e >= NE) return;
    if (g_fnode[erow[e]] == GEN) g_f1[ecol[e]] = GEN;
}

__global__ void mark_2hop_kernel(const int* __restrict__ erow,
                                 const int* __restrict__ ecol) {
    int e = blockIdx.x * blockDim.x + threadIdx.x;
    if (e >= NE) return;
    if (g_f1[erow[e]] == GEN) g_f2[ecol[e]] = GEN;
}

__global__ void compact_both_kernel() {
    int i = blockIdx.x * blockDim.x + threadIdx.x;
    if (i >= NV) return;
    if (g_f2[i] == GEN) {
        int p = atomicAdd(&g_n3, 1);
        g_list3[p] = i;
    }
    if (g_f1[i] == GEN) {
        int p = atomicAdd(&g_n1, 1);
        g_list1[p] = i;
    }
}

// ================= pipelined fp16 tensor-core GEMM ==========================
// C[M,N] = A[rows, K] @ B[K,N]; optional rowlist/pcount select A rows.
// bias added when non-null.
// mode 0: fp32   1: sigmoid fp32   2: sigmoid fp16   3: plain fp16
#define GS_ABUF 10240
#define GS_BBUF 12800
#define GS_BOFF (2 * GS_ABUF)                  // 20480
#define GS_TOTAL (GS_BOFF + 2 * GS_BBUF)       // 46080 dynamic

__global__ void __launch_bounds__(512)
gemm_f16_kernel(const __half* __restrict__ a16, int lda,
                const __half* __restrict__ bt, int ldb,
                float* __restrict__ C, int ldc,
                __half* __restrict__ o16, int ldo,
                const float* __restrict__ bias,
                const int* __restrict__ rowlist, const int* __restrict__ pcount,
                int M, int N, int K, int mode) {
    extern __shared__ __align__(16) char sm[];
    __shared__ int rows_sm[128];

    int cnt = pcount ? *pcount : M;
    int bm = blockIdx.y * 128;
    if (bm >= cnt) return;

    int tid = threadIdx.x;
    if (tid < 128) {
        int gi = bm + tid;
        if (gi > cnt - 1) gi = cnt - 1;
        rows_sm[tid] = rowlist ? rowlist[gi] : gi;
    }
    __syncthreads();

    int w = tid >> 5;
    int lane = tid & 31;
    int g = lane >> 2;
    int t2 = (lane & 3) * 2;

    int bn = blockIdx.x * 160;
    int m0 = (w & 3) * 32;
    int n0 = (w >> 2) * 40;
    int nch = K >> 5;

    float acc[2][5][4];
#pragma unroll
    for (int i = 0; i < 2; i++)
#pragma unroll
        for (int j = 0; j < 5; j++)
#pragma unroll
            for (int q = 0; q < 4; q++) acc[i][j][q] = 0.0f;

    auto prefetch = [&](int ch, int buf) {
        int k0 = ch * 32;
        {
            int r = tid >> 2;
            int c = tid & 3;
            size_t so = (size_t)rows_sm[r] * lda + k0 + c * 8;
            uint32_t d = cvta_shared_u32(sm + buf * GS_ABUF + (r * 40 + c * 8) * 2);
            cp_async16(d, a16 + so);
        }
#pragma unroll
        for (int it = 0; it < 2; it++) {
            int idx = tid + it * 512;
            if (idx < 640) {
                int r = idx >> 2;
                int c = idx & 3;
                size_t so = (size_t)(bn + r) * ldb + k0 + c * 8;
                uint32_t d = cvta_shared_u32(sm + GS_BOFF + buf * GS_BBUF +
                                             (r * 40 + c * 8) * 2);
                cp_async16(d, bt + so);
            }
        }
    };

    prefetch(0, 0);
    cp_commit();

    for (int ch = 0; ch < nch; ch++) {
        int buf = ch & 1;
        cp_wait0();
        __syncthreads();
        if (ch < nch - 1) {
            prefetch(ch + 1, buf ^ 1);
            cp_commit();
        }
        const __half* Af = reinterpret_cast<const __half*>(sm + buf * GS_ABUF);
        const __half* Bf = reinterpret_cast<const __half*>(sm + GS_BOFF + buf * GS_BBUF);

#pragma unroll
        for (int kc = 0; kc < 32; kc += 16) {
            uint32_t af[2][4];
#pragma unroll
            for (int i = 0; i < 2; i++) {
                int rm = m0 + i * 16;
                af[i][0] = *reinterpret_cast<const uint32_t*>(&Af[(rm + g)     * 40 + kc + t2]);
                af[i][1] = *reinterpret_cast<const uint32_t*>(&Af[(rm + g + 8) * 40 + kc + t2]);
                af[i][2] = *reinterpret_cast<const uint32_t*>(&Af[(rm + g)     * 40 + kc + t2 + 8]);
                af[i][3] = *reinterpret_cast<const uint32_t*>(&Af[(rm + g + 8) * 40 + kc + t2 + 8]);
            }
#pragma unroll
            for (int j = 0; j < 5; j++) {
                int rn = n0 + j * 8;
                uint32_t bf[2];
                bf[0] = *reinterpret_cast<const uint32_t*>(&Bf[(rn + g) * 40 + kc + t2]);
                bf[1] = *reinterpret_cast<const uint32_t*>(&Bf[(rn + g) * 40 + kc + t2 + 8]);
#pragma unroll
                for (int i = 0; i < 2; i++)
                    mma16816(acc[i][j], af[i], bf);
            }
        }
        __syncthreads();
    }

    // ---- epilogue ----
#pragma unroll
    for (int i = 0; i < 2; i++) {
#pragma unroll
        for (int j = 0; j < 5; j++) {
            int gn = bn + n0 + j * 8 + t2;
            if (gn >= N) continue;      // N even, gn even -> gn+1 safe
#pragma unroll
            for (int half = 0; half < 2; half++) {
                int gm = bm + m0 + i * 16 + g + half * 8;
                if (gm >= cnt) continue;
                int gr = rows_sm[gm - bm];
                float2 o;
                o.x = acc[i][j][half * 2 + 0];
                o.y = acc[i][j][half * 2 + 1];
                if (bias) {
                    o.x += bias[gn];
                    o.y += bias[gn + 1];
                }
                if (mode == 1 || mode == 2) {
                    o.x = 1.0f / (1.0f + __expf(-o.x));
                    o.y = 1.0f / (1.0f + __expf(-o.y));
                }
                if (mode >= 2) {
                    __half2 hv = __floats2half2_rn(o.x, o.y);
                    *reinterpret_cast<uint32_t*>(&o16[(size_t)gr * ldo + gn]) =
                        *reinterpret_cast<uint32_t*>(&hv);
                } else {
                    *reinterpret_cast<float2*>(C + (size_t)gr * ldc + gn) = o;
                }
            }
        }
    }
}

// ================= graph preprocessing (shortened chain) =====================
__global__ void zero_both_kernel() {
    int i = blockIdx.x * blockDim.x + threadIdx.x;
    if (i < NV) { g_cnt[i] = 0; g_cursor[i] = 0; }
}

__global__ void count_kernel(const int* __restrict__ erow) {
    int e = blockIdx.x * blockDim.x + threadIdx.x;
    if (e < NE) atomicAdd(&g_cnt[erow[e]], 1);
}

// shuffle-based two-level block scan over 1024 elems (2 syncthreads)
__global__ void scanA_kernel() {
    __shared__ int ws[32];
    int i = blockIdx.x * 1024 + threadIdx.x;
    int lane = threadIdx.x & 31;
    int wid = threadIdx.x >> 5;
    int v = (i < NV) ? g_cnt[i] : 0;
    int x = v;
#pragma unroll
    for (int o = 1; o < 32; o <<= 1) {
        int t = __shfl_up_sync(0xFFFFFFFFu, x, o);
        if (lane >= o) x += t;
    }
    if (lane == 31) ws[wid] = x;
    __syncthreads();
    if (wid == 0) {
        int y = ws[lane];
#pragma unroll
        for (int o = 1; o < 32; o <<= 1) {
            int t = __shfl_up_sync(0xFFFFFFFFu, y, o);
            if (lane >= o) y += t;
        }
        ws[lane] = y;
    }
    __syncthreads();
    int base = (wid > 0) ? ws[wid - 1] : 0;
    int incl = base + x;
    if (i < NV) g_rowstart[i] = incl - v;   // exclusive
    if (threadIdx.x == 1023) g_tot[blockIdx.x] = incl;
}

__global__ void scanB_kernel() {
    __shared__ int s[128];
    int v = (threadIdx.x < NBLK_SCAN) ? g_tot[threadIdx.x] : 0;
    s[threadIdx.x] = v;
    __syncthreads();
    for (int o = 1; o < 128; o <<= 1) {
        int t = 0;
        if (threadIdx.x >= o) t = s[threadIdx.x - o];
        __syncthreads();
        if (threadIdx.x >= o) s[threadIdx.x] += t;
        __syncthreads();
    }
    if (threadIdx.x < NBLK_SCAN) g_tot[threadIdx.x] = s[threadIdx.x] - v;
}

__global__ void scanC_kernel() {
    int i = blockIdx.x * blockDim.x + threadIdx.x;
    if (i < NV) g_rowstart[i] += g_tot[i >> 10];
    if (i == 0) g_rowstart[NV] = NE;
}

// scatter + inline normalization values (vals kernel folded in)
__global__ void scatter_kernel(const int* __restrict__ erow, const int* __restrict__ ecol) {
    int e = blockIdx.x * blockDim.x + threadIdx.x;
    if (e >= NE) return;
    int r = erow[e];
    int c = ecol[e];
    int pos = g_rowstart[r] + atomicAdd(&g_cursor[r], 1);
    g_scol[pos] = c;
    int dc = g_cnt[c];
    float val = 0.0f;
    if (dc > 0)
        val = rsqrtf((float)g_cnt[r]) * rsqrtf((float)dc);   // cnt[r] >= 1 here
    g_sval[pos] = val;
}

// ================= fp16 pull SpMM (LINEAR — no sigmoid) =====================
__device__ __forceinline__ void fma8(float* acc, uint4 t, float v) {
    __half2 p;
    float2 f;
    *reinterpret_cast<uint32_t*>(&p) = t.x; f = __half22float2(p);
    acc[0] += v * f.x; acc[1] += v * f.y;
    *reinterpret_cast<uint32_t*>(&p) = t.y; f = __half22float2(p);
    acc[2] += v * f.x; acc[3] += v * f.y;
    *reinterpret_cast<uint32_t*>(&p) = t.z; f = __half22float2(p);
    acc[4] += v * f.x; acc[5] += v * f.y;
    *reinterpret_cast<uint32_t*>(&p) = t.w; f = __half22float2(p);
    acc[6] += v * f.x; acc[7] += v * f.y;
}

__device__ __forceinline__ void spmm_accum(const __half* __restrict__ X,
                                           int row, int lane, bool lo8,
                                           float* a, float* b) {
    int s = g_rowstart[row];
    int e = g_rowstart[row + 1];
    int j = s;
    for (; j + 1 < e; j += 2) {
        int c0 = g_scol[j];
        float v0 = g_sval[j];
        int c1 = g_scol[j + 1];
        float v1 = g_sval[j + 1];
        const uint4* x0 = reinterpret_cast<const uint4*>(X + (size_t)c0 * AP);
        const uint4* x1 = reinterpret_cast<const uint4*>(X + (size_t)c1 * AP);
        uint4 t0 = x0[lane];
        uint4 t1 = x1[lane];
        fma8(a, t0, v0);
        fma8(a, t1, v1);
        if (lo8) {
            uint4 s0 = x0[32 + lane];
            uint4 s1 = x1[32 + lane];
            fma8(b, s0, v0);
            fma8(b, s1, v1);
        }
    }
    if (j < e) {
        int c = g_scol[j];
        float v = g_sval[j];
        const uint4* x4 = reinterpret_cast<const uint4*>(X + (size_t)c * AP);
        fma8(a, x4[lane], v);
        if (lo8) fma8(b, x4[32 + lane], v);
    }
}

__device__ __forceinline__ void spmm_store_lin(__half* __restrict__ O, int orow,
                                               int lane, bool lo8,
                                               const float* a, const float* b) {
    __half2 h0 = __floats2half2_rn(a[0], a[1]);
    __half2 h1 = __floats2half2_rn(a[2], a[3]);
    __half2 h2 = __floats2half2_rn(a[4], a[5]);
    __half2 h3 = __floats2half2_rn(a[6], a[7]);
    uint4 pk;
    pk.x = *reinterpret_cast<uint32_t*>(&h0);
    pk.y = *reinterpret_cast<uint32_t*>(&h1);
    pk.z = *reinterpret_cast<uint32_t*>(&h2);
    pk.w = *reinterpret_cast<uint32_t*>(&h3);
    __stcs(reinterpret_cast<uint4*>(O + (size_t)orow * AP) + lane, pk);
    if (lo8) {
        h0 = __floats2half2_rn(b[0], b[1]);
        h1 = __floats2half2_rn(b[2], b[3]);
        h2 = __floats2half2_rn(b[4], b[5]);
        h3 = __floats2half2_rn(b[6], b[7]);
        pk.x = *reinterpret_cast<uint32_t*>(&h0);
        pk.y = *reinterpret_cast<uint32_t*>(&h1);
        pk.z = *reinterpret_cast<uint32_t*>(&h2);
        pk.w = *reinterpret_cast<uint32_t*>(&h3);
        __stcs(reinterpret_cast<uint4*>(O + (size_t)orow * AP) + 32 + lane, pk);
    }
}

__global__ void spmm_sc_kernel(const __half* __restrict__ X, __half* __restrict__ O,
                               const int* __restrict__ rowlist,
                               const int* __restrict__ pcount) {
    int widx = (blockIdx.x * blockDim.x + threadIdx.x) >> 5;
    int lane = threadIdx.x & 31;
    int cnt = *pcount;
    if (widx >= cnt) return;
    int row = rowlist[widx];
    bool lo8 = lane < 8;
    float a[8] = {0,0,0,0,0,0,0,0};
    float b[8] = {0,0,0,0,0,0,0,0};
    spmm_accum(X, row, lane, lo8, a, b);
    spmm_store_lin(O, row, lane, lo8, a, b);
}

__global__ void spmm_dn_kernel(const __half* __restrict__ X, __half* __restrict__ O,
                               const int* __restrict__ node) {
    int b = (blockIdx.x * blockDim.x + threadIdx.x) >> 5;
    int lane = threadIdx.x & 31;
    if (b >= BATCH) return;
    int row = node[b];
    bool lo8 = lane < 8;
    float a[8] = {0,0,0,0,0,0,0,0};
    float bb[8] = {0,0,0,0,0,0,0,0};
    spmm_accum(X, row, lane, lo8, a, bb);
    spmm_store_lin(O, b, lane, lo8, a, bb);
}

// final layer
__global__ void final_kernel(const float* __restrict__ h,
                             const float* __restrict__ Wc,
                             const float* __restrict__ bc,
                             float* __restrict__ out) {
    int warp = (blockIdx.x * blockDim.x + threadIdx.x) >> 5;
    int lane = threadIdx.x & 31;
    if (warp >= BATCH) return;
    const float* hr = h + (size_t)warp * HID;
    float a0 = 0.f, a1 = 0.f;
    for (int k = lane; k < HID; k += 32) {
        float hv = hr[k];
        a0 += hv * Wc[k * 2 + 0];
        a1 += hv * Wc[k * 2 + 1];
    }
#pragma unroll
    for (int o = 16; o > 0; o >>= 1) {
        a0 += __shfl_down_sync(0xFFFFFFFFu, a0, o);
        a1 += __shfl_down_sync(0xFFFFFFFFu, a1, o);
    }
    if (lane == 0) {
        out[warp * 2 + 0] = a0 + bc[0];
        out[warp * 2 + 1] = a1 + bc[1];
    }
}

// ================= host launch =================
extern "C" void kernel_launch(void* const* d_in, const int* in_sizes, int n_in,
                              void* d_out, int out_size) {
    const float* input = (const float*)d_in[0];
    const int*   node  = (const int*)d_in[1];
    const int*   erow  = (const int*)d_in[2];
    const int*   ecol  = (const int*)d_in[3];
    const float* H0    = (const float*)d_in[4];
    const float* W1    = (const float*)d_in[5];
    const float* W2    = (const float*)d_in[6];
    const float* Wa    = (const float*)d_in[7];
    const float* ba    = (const float*)d_in[8];
    const float* Wb    = (const float*)d_in[9];
    const float* bb    = (const float*)d_in[10];
    const float* Wc    = (const float*)d_in[11];
    const float* bc    = (const float*)d_in[12];
    float*       out   = (float*)d_out;

    void *p_h2;
    void *p_act, *p_x16, *p_w1t, *p_w2t, *p_fcf16, *p_wat, *p_wbt, *p_h1f16;
    void *p_list1, *p_list3, *p_n1, *p_n3;
    cudaGetSymbolAddress(&p_h2,     g_h2);
    cudaGetSymbolAddress(&p_act,    g_act);
    cudaGetSymbolAddress(&p_x16,    g_x16);
    cudaGetSymbolAddress(&p_w1t,    g_w1t);
    cudaGetSymbolAddress(&p_w2t,    g_w2t);
    cudaGetSymbolAddress(&p_fcf16,  g_fcf16);
    cudaGetSymbolAddress(&p_wat,    g_wat);
    cudaGetSymbolAddress(&p_wbt,    g_wbt);
    cudaGetSymbolAddress(&p_h1f16,  g_h1f16);
    cudaGetSymbolAddress(&p_list1,  g_list1);
    cudaGetSymbolAddress(&p_list3,  g_list3);
    cudaGetSymbolAddress(&p_n1,     g_n1);
    cudaGetSymbolAddress(&p_n3,     g_n3);

    float* h2 = (float*)p_h2;

    cudaFuncSetAttribute(gemm_f16_kernel,
                         cudaFuncAttributeMaxDynamicSharedMemorySize, GS_TOTAL);

    static cudaStream_t s2 = nullptr, s3 = nullptr;
    static cudaEvent_t evF = nullptr, evAct = nullptr, evCsr = nullptr;
    if (!s2) {
        cudaStreamCreateWithFlags(&s2, cudaStreamNonBlocking);
        cudaStreamCreateWithFlags(&s3, cudaStreamNonBlocking);
        cudaEventCreateWithFlags(&evF, cudaEventDisableTiming);
        cudaEventCreateWithFlags(&evAct, cudaEventDisableTiming);
        cudaEventCreateWithFlags(&evCsr, cudaEventDisableTiming);
    }

    const int TPB = 256;
    const int nvBlocks = (NV + TPB - 1) / TPB;
    const int neBlocks = (NE + TPB - 1) / TPB;

    cudaEventRecord(evF, 0);

    // ---- s2: frontier construction + pre_act (sole consumer of list3) ----
    cudaStreamWaitEvent(s2, evF, 0);
    mark_node_kernel<<<(BATCH + TPB - 1) / TPB, TPB, 0, s2>>>(node);
    mark_1hop_kernel<<<neBlocks, TPB, 0, s2>>>(erow, ecol);
    mark_2hop_kernel<<<neBlocks, TPB, 0, s2>>>(erow, ecol);
    compact_both_kernel<<<nvBlocks, TPB, 0, s2>>>();
    pre_act_list_kernel<<<(NV * 75 + TPB - 1) / TPB, TPB, 0, s2>>>(
        H0, (int*)p_list3, (int*)p_n3);
    cudaEventRecord(evAct, s2);

    // ---- s3: shortened CSR build ----
    cudaStreamWaitEvent(s3, evF, 0);
    zero_both_kernel<<<nvBlocks, TPB, 0, s3>>>();
    count_kernel<<<neBlocks, TPB, 0, s3>>>(erow);
    scanA_kernel<<<NBLK_SCAN, 1024, 0, s3>>>();
    scanB_kernel<<<1, 128, 0, s3>>>();
    scanC_kernel<<<nvBlocks, TPB, 0, s3>>>();
    scatter_kernel<<<neBlocks, TPB, 0, s3>>>(erow, ecol);
    cudaEventRecord(evCsr, s3);

    // ---- main stream: weight + input conversions ----
    pre_wT_kernel<<<(EMB * EMB + TPB - 1) / TPB, TPB>>>(W1, EMB, EMB, AP, (__half*)p_w1t);
    pre_wT_kernel<<<(EMB * EMB + TPB - 1) / TPB, TPB>>>(W2, EMB, EMB, AP, (__half*)p_w2t);
    pre_wT_kernel<<<(FCK * HID + TPB - 1) / TPB, TPB>>>(Wa, FCK, HID, FCP, (__half*)p_wat);
    pre_wT_kernel<<<(HID * HID + TPB - 1) / TPB, TPB>>>(Wb, HID, HID, HP, (__half*)p_wbt);
    pre_input_f16_kernel<<<(BATCH * 192 + TPB - 1) / TPB, TPB>>>(input);

    // ---- join act + CSR, then Y = A*H0 on S1 rows (linear, fp16) ----
    cudaStreamWaitEvent(0, evAct, 0);
    cudaStreamWaitEvent(0, evCsr, 0);
    int spmmBlocks = (NV * 32 + TPB - 1) / TPB;
    spmm_sc_kernel<<<spmmBlocks, TPB>>>((__half*)p_act, (__half*)p_x16,
                                        (int*)p_list1, (int*)p_n1);

    // ---- H1 = sigmoid(Y @ W1) on S1 rows ----
    dim3 gbig(2, (NV + 127) / 128);
    gemm_f16_kernel<<<gbig, 512, GS_TOTAL>>>(
        (__half*)p_x16, AP, (__half*)p_w1t, AP,
        nullptr, 0, (__half*)p_act, AP, nullptr,
        (int*)p_list1, (int*)p_n1, NV, EMB, AP, 2);

    // ---- Z = A*H1 at node rows, densely packed ----
    spmm_dn_kernel<<<(BATCH * 32 + TPB - 1) / TPB, TPB>>>(
        (__half*)p_act, (__half*)p_x16, node);

    // ---- fc[:, 0:300] = sigmoid(Z @ W2) ----
    dim3 g2(2, BATCH / 128);
    gemm_f16_kernel<<<g2, 512, GS_TOTAL>>>(
        (__half*)p_x16, AP, (__half*)p_w2t, AP,
        nullptr, 0, (__half*)p_fcf16, FCP, nullptr,
        nullptr, nullptr, BATCH, EMB, AP, 2);

    // ---- MLP head ----
    dim3 gmlp(4, BATCH / 128);
    gemm_f16_kernel<<<gmlp, 512, GS_TOTAL>>>(
        (__half*)p_fcf16, FCP, (__half*)p_wat, FCP,
        nullptr, 0, (__half*)p_h1f16, HP, ba,
        nullptr, nullptr, BATCH, HID, FCP, 2);
    gemm_f16_kernel<<<gmlp, 512, GS_TOTAL>>>(
        (__half*)p_h1f16, HP, (__half*)p_wbt, HP,
        h2, HID, nullptr, 0, bb,
        nullptr, nullptr, BATCH, HID, HP, 1);

    final_kernel<<<(BATCH * 32 + TPB - 1) / TPB, TPB>>>(h2, Wc, bc, out);
}

// round 16
// speedup vs baseline: 1.1098x; 1.0407x over previous
#include <cuda_runtime.h>
#include <cuda_fp16.h>
#include <math.h>
#include <cstdint>

#define NV 117000
#define NE 468000
#define EMB 300
#define IN_DIM 768
#define BATCH 4096
#define HID 500
#define FCK (EMB + IN_DIM)   // 1068
#define NBLK_SCAN ((NV + 1023) / 1024)   // 115
#define AP 320               // padded fp16 stride for GCN activations/weights
#define FCP 1088             // padded fc width
#define HP 512               // padded hidden width
#define BNROWS 640           // padded N-rows for transposed MLP weights
#define GEN 1                // constant generation stamp (mark-only flags)

// ---------------- device scratch (allocation-free, zero-initialized) -------
__device__ int   g_cnt[NV];
__device__ int   g_rowstart[NV + 1];
__device__ int   g_tot[256];
__device__ int   g_cursor[NV];
__device__ int   g_scol[NE];
__device__ float g_sval[NE];
// frontier machinery
__device__ int   g_fnode[NV];
__device__ int   g_f1[NV];       // S1 (1-hop)
__device__ int   g_f2[NV];       // S2 (2-hop)
__device__ int   g_list1[NV];    // compacted S1
__device__ int   g_list3[NV];    // compacted S2
__device__ int   g_n1;
__device__ int   g_n3;
// fp16 buffers (pads stay statically zero — never written with nonzero)
__device__ __half g_act[(size_t)NV * AP];           // H0 f16 / H1 (S1 rows)
__device__ __half g_x16[(size_t)NV * AP];           // Y = A*H0 (S1) / Z dense
__device__ __half g_w1t[AP * AP];
__device__ __half g_w2t[AP * AP];
__device__ __half g_fcf16[(size_t)BATCH * FCP];
__device__ __half g_wat[(size_t)BNROWS * FCP];
__device__ __half g_wbt[(size_t)BNROWS * HP];
__device__ __half g_h1f16[(size_t)BATCH * HP];

// ================= helpers =================
__device__ __forceinline__ void mma16816(float* c, const uint32_t* a, const uint32_t* b) {
    asm volatile(
        "mma.sync.aligned.m16n8k16.row.col.f32.f16.f16.f32 "
        "{%0,%1,%2,%3}, {%4,%5,%6,%7}, {%8,%9}, {%0,%1,%2,%3};"
        : "+f"(c[0]), "+f"(c[1]), "+f"(c[2]), "+f"(c[3])
        : "r"(a[0]), "r"(a[1]), "r"(a[2]), "r"(a[3]),
          "r"(b[0]), "r"(b[1]));
}

__device__ __forceinline__ uint32_t cvta_shared_u32(const void* p) {
    uint32_t a;
    asm("{ .reg .u64 t; cvta.to.shared.u64 t, %1; cvt.u32.u64 %0, t; }"
        : "=r"(a) : "l"(p));
    return a;
}

__device__ __forceinline__ void cp_async16(uint32_t dst, const void* src) {
    asm volatile("cp.async.ca.shared.global [%0], [%1], 16;" :: "r"(dst), "l"(src));
}
__device__ __forceinline__ void cp_commit() {
    asm volatile("cp.async.commit_group;");
}
__device__ __forceinline__ void cp_wait0() {
    asm volatile("cp.async.wait_group 0;");
}

// ================= prep kernels =================
__global__ void pre_act_list_kernel(const float* __restrict__ X,
                                    const int* __restrict__ rowlist,
                                    const int* __restrict__ pcount) {
    int idx = blockIdx.x * blockDim.x + threadIdx.x;
    int cnt = *pcount;
    int i = idx / 75;
    if (i >= cnt) return;
    int q = idx - i * 75;
    int r = rowlist[i];
    float4 v = reinterpret_cast<const float4*>(X)[(size_t)r * 75 + q];
    __half2 p0 = __floats2half2_rn(v.x, v.y);
    __half2 p1 = __floats2half2_rn(v.z, v.w);
    uint2 pk = make_uint2(*reinterpret_cast<uint32_t*>(&p0),
                          *reinterpret_cast<uint32_t*>(&p1));
    *reinterpret_cast<uint2*>(&g_act[(size_t)r * AP + q * 4]) = pk;
}

__global__ void pre_wT_kernel(const float* __restrict__ W, int K, int N, int ldo,
                              __half* __restrict__ t16) {
    int idx = blockIdx.x * blockDim.x + threadIdx.x;
    if (idx >= K * N) return;
    int k = idx / N;
    int n = idx - k * N;
    t16[(size_t)n * ldo + k] = __float2half_rn(W[idx]);
}

// input fp32 [BATCH, IN_DIM] -> fc columns [EMB, EMB+IN_DIM) as fp16
__global__ void pre_input_f16_kernel(const float* __restrict__ input) {
    int idx = blockIdx.x * blockDim.x + threadIdx.x;
    if (idx >= BATCH * 192) return;
    int b = idx / 192;
    int q = idx - b * 192;
    float4 v = reinterpret_cast<const float4*>(input)[(size_t)b * 192 + q];
    __half2 p0 = __floats2half2_rn(v.x, v.y);
    __half2 p1 = __floats2half2_rn(v.z, v.w);
    uint2 pk = make_uint2(*reinterpret_cast<uint32_t*>(&p0),
                          *reinterpret_cast<uint32_t*>(&p1));
    *reinterpret_cast<uint2*>(&g_fcf16[(size_t)b * FCP + EMB + q * 4]) = pk;
}

// out[b, 0:2] = bc  (MLP-G2 epilogue accumulates into it)
__global__ void init_out_kernel(float* __restrict__ out, const float* __restrict__ bc) {
    int i = blockIdx.x * blockDim.x + threadIdx.x;
    if (i < BATCH * 2) out[i] = bc[i & 1];
}

// ================= frontier kernels (ILP-4) =================
__global__ void mark_node_kernel(const int* __restrict__ node) {
    int i = blockIdx.x * blockDim.x + threadIdx.x;
    if (i == 0) { g_n1 = 0; g_n3 = 0; }
    if (i < BATCH) g_fnode[node[i]] = GEN;
}

__global__ void mark_1hop_kernel(const int* __restrict__ erow,
                                 const int* __restrict__ ecol) {
    int e = (blockIdx.x * blockDim.x + threadIdx.x) * 4;   // NE % 4 == 0
    if (e >= NE) return;
    int r0 = erow[e + 0], r1 = erow[e + 1], r2 = erow[e + 2], r3 = erow[e + 3];
    int f0 = g_fnode[r0], f1 = g_fnode[r1], f2 = g_fnode[r2], f3 = g_fnode[r3];
    if (f0 == GEN) g_f1[ecol[e + 0]] = GEN;
    if (f1 == GEN) g_f1[ecol[e + 1]] = GEN;
    if (f2 == GEN) g_f1[ecol[e + 2]] = GEN;
    if (f3 == GEN) g_f1[ecol[e + 3]] = GEN;
}

__global__ void mark_2hop_kernel(const int* __restrict__ erow,
                                 const int* __restrict__ ecol) {
    int e = (blockIdx.x * blockDim.x + threadIdx.x) * 4;
    if (e >= NE) return;
    int r0 = erow[e + 0], r1 = erow[e + 1], r2 = erow[e + 2], r3 = erow[e + 3];
    int f0 = g_f1[r0], f1 = g_f1[r1], f2 = g_f1[r2], f3 = g_f1[r3];
    if (f0 == GEN) g_f2[ecol[e + 0]] = GEN;
    if (f1 == GEN) g_f2[ecol[e + 1]] = GEN;
    if (f2 == GEN) g_f2[ecol[e + 2]] = GEN;
    if (f3 == GEN) g_f2[ecol[e + 3]] = GEN;
}

__global__ void compact_both_kernel() {
    int i = (blockIdx.x * blockDim.x + threadIdx.x) * 4;   // NV % 4 == 0? 117000/4 = 29250 ✓
    if (i >= NV) return;
#pragma unroll
    for (int t = 0; t < 4; t++) {
        int k = i + t;
        if (g_f2[k] == GEN) {
            int p = atomicAdd(&g_n3, 1);
            g_list3[p] = k;
        }
        if (g_f1[k] == GEN) {
            int p = atomicAdd(&g_n1, 1);
            g_list1[p] = k;
        }
    }
}

// ================= pipelined fp16 tensor-core GEMM ==========================
// C[M,N] = A[rows, K] @ B[K,N]; optional rowlist/pcount select A rows.
// bias added when non-null.
// mode 0: fp32   1: sigmoid fp32   2: sigmoid fp16   3: plain fp16
// mode 5: bias+sigmoid, then out[row,0:2] += sig .dot Wc rows (fused final)
#define GS_ABUF 10240
#define GS_BBUF 12800
#define GS_BOFF (2 * GS_ABUF)                  // 20480
#define GS_TOTAL (GS_BOFF + 2 * GS_BBUF)       // 46080 dynamic

__global__ void __launch_bounds__(512)
gemm_f16_kernel(const __half* __restrict__ a16, int lda,
                const __half* __restrict__ bt, int ldb,
                float* __restrict__ C, int ldc,
                __half* __restrict__ o16, int ldo,
                const float* __restrict__ bias,
                const int* __restrict__ rowlist, const int* __restrict__ pcount,
                const float* __restrict__ wc, float* __restrict__ outp,
                int M, int N, int K, int mode) {
    extern __shared__ __align__(16) char sm[];
    __shared__ int rows_sm[128];
    __shared__ float psum[256];

    int cnt = pcount ? *pcount : M;
    int bm = blockIdx.y * 128;
    if (bm >= cnt) return;

    int tid = threadIdx.x;
    if (tid < 128) {
        int gi = bm + tid;
        if (gi > cnt - 1) gi = cnt - 1;
        rows_sm[tid] = rowlist ? rowlist[gi] : gi;
    }
    if (mode == 5 && tid < 256) psum[tid] = 0.0f;
    __syncthreads();

    int w = tid >> 5;
    int lane = tid & 31;
    int g = lane >> 2;
    int t2 = (lane & 3) * 2;

    int bn = blockIdx.x * 160;
    int m0 = (w & 3) * 32;
    int n0 = (w >> 2) * 40;
    int nch = K >> 5;

    float acc[2][5][4];
#pragma unroll
    for (int i = 0; i < 2; i++)
#pragma unroll
        for (int j = 0; j < 5; j++)
#pragma unroll
            for (int q = 0; q < 4; q++) acc[i][j][q] = 0.0f;

    auto prefetch = [&](int ch, int buf) {
        int k0 = ch * 32;
        {
            int r = tid >> 2;
            int c = tid & 3;
            size_t so = (size_t)rows_sm[r] * lda + k0 + c * 8;
            uint32_t d = cvta_shared_u32(sm + buf * GS_ABUF + (r * 40 + c * 8) * 2);
            cp_async16(d, a16 + so);
        }
#pragma unroll
        for (int it = 0; it < 2; it++) {
            int idx = tid + it * 512;
            if (idx < 640) {
                int r = idx >> 2;
                int c = idx & 3;
                size_t so = (size_t)(bn + r) * ldb + k0 + c * 8;
                uint32_t d = cvta_shared_u32(sm + GS_BOFF + buf * GS_BBUF +
                                             (r * 40 + c * 8) * 2);
                cp_async16(d, bt + so);
            }
        }
    };

    prefetch(0, 0);
    cp_commit();

    for (int ch = 0; ch < nch; ch++) {
        int buf = ch & 1;
        cp_wait0();
        __syncthreads();
        if (ch < nch - 1) {
            prefetch(ch + 1, buf ^ 1);
            cp_commit();
        }
        const __half* Af = reinterpret_cast<const __half*>(sm + buf * GS_ABUF);
        const __half* Bf = reinterpret_cast<const __half*>(sm + GS_BOFF + buf * GS_BBUF);

#pragma unroll
        for (int kc = 0; kc < 32; kc += 16) {
            uint32_t af[2][4];
#pragma unroll
            for (int i = 0; i < 2; i++) {
                int rm = m0 + i * 16;
                af[i][0] = *reinterpret_cast<const uint32_t*>(&Af[(rm + g)     * 40 + kc + t2]);
                af[i][1] = *reinterpret_cast<const uint32_t*>(&Af[(rm + g + 8) * 40 + kc + t2]);
                af[i][2] = *reinterpret_cast<const uint32_t*>(&Af[(rm + g)     * 40 + kc + t2 + 8]);
                af[i][3] = *reinterpret_cast<const uint32_t*>(&Af[(rm + g + 8) * 40 + kc + t2 + 8]);
            }
#pragma unroll
            for (int j = 0; j < 5; j++) {
                int rn = n0 + j * 8;
                uint32_t bf[2];
                bf[0] = *reinterpret_cast<const uint32_t*>(&Bf[(rn + g) * 40 + kc + t2]);
                bf[1] = *reinterpret_cast<const uint32_t*>(&Bf[(rn + g) * 40 + kc + t2 + 8]);
#pragma unroll
                for (int i = 0; i < 2; i++)
                    mma16816(acc[i][j], af[i], bf);
            }
        }
        __syncthreads();
    }

    // ---- epilogue ----
    if (mode == 5) {
        // fused: sig = sigmoid(acc + bias); psum[row][c] += sig . Wc[:,c]
#pragma unroll
        for (int i = 0; i < 2; i++) {
#pragma unroll
            for (int half = 0; half < 2; half++) {
                float s0 = 0.0f, s1 = 0.0f;
#pragma unroll
                for (int j = 0; j < 5; j++) {
                    int gn = bn + n0 + j * 8 + t2;
                    if (gn >= N) continue;
                    float ox = acc[i][j][half * 2 + 0] + bias[gn];
                    float oy = acc[i][j][half * 2 + 1] + bias[gn + 1];
                    ox = 1.0f / (1.0f + __expf(-ox));
                    oy = 1.0f / (1.0f + __expf(-oy));
                    s0 += ox * wc[gn * 2 + 0] + oy * wc[gn * 2 + 2];
                    s1 += ox * wc[gn * 2 + 1] + oy * wc[gn * 2 + 3];
                }
                int rl = m0 + i * 16 + g + half * 8;
                atomicAdd(&psum[rl * 2 + 0], s0);
                atomicAdd(&psum[rl * 2 + 1], s1);
            }
        }
        __syncthreads();
        if (tid < 256) {
            int rl = tid >> 1;
            int c = tid & 1;
            atomicAdd(&outp[(size_t)(bm + rl) * 2 + c], psum[tid]);
        }
        return;
    }

#pragma unroll
    for (int i = 0; i < 2; i++) {
#pragma unroll
        for (int j = 0; j < 5; j++) {
            int gn = bn + n0 + j * 8 + t2;
            if (gn >= N) continue;      // N even, gn even -> gn+1 safe
#pragma unroll
            for (int half = 0; half < 2; half++) {
                int gm = bm + m0 + i * 16 + g + half * 8;
                if (gm >= cnt) continue;
                int gr = rows_sm[gm - bm];
                float2 o;
                o.x = acc[i][j][half * 2 + 0];
                o.y = acc[i][j][half * 2 + 1];
                if (bias) {
                    o.x += bias[gn];
                    o.y += bias[gn + 1];
                }
                if (mode == 1 || mode == 2) {
                    o.x = 1.0f / (1.0f + __expf(-o.x));
                    o.y = 1.0f / (1.0f + __expf(-o.y));
                }
                if (mode >= 2) {
                    __half2 hv = __floats2half2_rn(o.x, o.y);
                    *reinterpret_cast<uint32_t*>(&o16[(size_t)gr * ldo + gn]) =
                        *reinterpret_cast<uint32_t*>(&hv);
                } else {
                    *reinterpret_cast<float2*>(C + (size_t)gr * ldc + gn) = o;
                }
            }
        }
    }
}

// ================= graph preprocessing (shortened chain, ILP-4) =============
__global__ void zero_both_kernel() {
    int i = blockIdx.x * blockDim.x + threadIdx.x;
    if (i < NV) { g_cnt[i] = 0; g_cursor[i] = 0; }
}

__global__ void count_kernel(const int* __restrict__ erow) {
    int e = (blockIdx.x * blockDim.x + threadIdx.x) * 4;
    if (e >= NE) return;
    int r0 = erow[e + 0], r1 = erow[e + 1], r2 = erow[e + 2], r3 = erow[e + 3];
    atomicAdd(&g_cnt[r0], 1);
    atomicAdd(&g_cnt[r1], 1);
    atomicAdd(&g_cnt[r2], 1);
    atomicAdd(&g_cnt[r3], 1);
}

// shuffle-based two-level block scan over 1024 elems (2 syncthreads)
__global__ void scanA_kernel() {
    __shared__ int ws[32];
    int i = blockIdx.x * 1024 + threadIdx.x;
    int lane = threadIdx.x & 31;
    int wid = threadIdx.x >> 5;
    int v = (i < NV) ? g_cnt[i] : 0;
    int x = v;
#pragma unroll
    for (int o = 1; o < 32; o <<= 1) {
        int t = __shfl_up_sync(0xFFFFFFFFu, x, o);
        if (lane >= o) x += t;
    }
    if (lane == 31) ws[wid] = x;
    __syncthreads();
    if (wid == 0) {
        int y = ws[lane];
#pragma unroll
        for (int o = 1; o < 32; o <<= 1) {
            int t = __shfl_up_sync(0xFFFFFFFFu, y, o);
            if (lane >= o) y += t;
        }
        ws[lane] = y;
    }
    __syncthreads();
    int base = (wid > 0) ? ws[wid - 1] : 0;
    int incl = base + x;
    if (i < NV) g_rowstart[i] = incl - v;   // exclusive
    if (threadIdx.x == 1023) g_tot[blockIdx.x] = incl;
}

__global__ void scanB_kernel() {
    __shared__ int s[128];
    int v = (threadIdx.x < NBLK_SCAN) ? g_tot[threadIdx.x] : 0;
    s[threadIdx.x] = v;
    __syncthreads();
    for (int o = 1; o < 128; o <<= 1) {
        int t = 0;
        if (threadIdx.x >= o) t = s[threadIdx.x - o];
        __syncthreads();
        if (threadIdx.x >= o) s[threadIdx.x] += t;
        __syncthreads();
    }
    if (threadIdx.x < NBLK_SCAN) g_tot[threadIdx.x] = s[threadIdx.x] - v;
}

__global__ void scanC_kernel() {
    int i = blockIdx.x * blockDim.x + threadIdx.x;
    if (i < NV) g_rowstart[i] += g_tot[i >> 10];
    if (i == 0) g_rowstart[NV] = NE;
}

// scatter + inline normalization values (ILP-4)
__global__ void scatter_kernel(const int* __restrict__ erow, const int* __restrict__ ecol) {
    int e = (blockIdx.x * blockDim.x + threadIdx.x) * 4;
    if (e >= NE) return;
#pragma unroll
    for (int t = 0; t < 4; t++) {
        int k = e + t;
        int r = erow[k];
        int c = ecol[k];
        int pos = g_rowstart[r] + atomicAdd(&g_cursor[r], 1);
        g_scol[pos] = c;
        int dc = g_cnt[c];
        float val = 0.0f;
        if (dc > 0)
            val = rsqrtf((float)g_cnt[r]) * rsqrtf((float)dc);
        g_sval[pos] = val;
    }
}

// ================= fp16 pull SpMM (LINEAR — no sigmoid) =====================
__device__ __forceinline__ void fma8(float* acc, uint4 t, float v) {
    __half2 p;
    float2 f;
    *reinterpret_cast<uint32_t*>(&p) = t.x; f = __half22float2(p);
    acc[0] += v * f.x; acc[1] += v * f.y;
    *reinterpret_cast<uint32_t*>(&p) = t.y; f = __half22float2(p);
    acc[2] += v * f.x; acc[3] += v * f.y;
    *reinterpret_cast<uint32_t*>(&p) = t.z; f = __half22float2(p);
    acc[4] += v * f.x; acc[5] += v * f.y;
    *reinterpret_cast<uint32_t*>(&p) = t.w; f = __half22float2(p);
    acc[6] += v * f.x; acc[7] += v * f.y;
}

__device__ __forceinline__ void spmm_accum(const __half* __restrict__ X,
                                           int row, int lane, bool lo8,
                                           float* a, float* b) {
    int s = g_rowstart[row];
    int e = g_rowstart[row + 1];
    int j = s;
    for (; j + 1 < e; j += 2) {
        int c0 = g_scol[j];
        float v0 = g_sval[j];
        int c1 = g_scol[j + 1];
        float v1 = g_sval[j + 1];
        const uint4* x0 = reinterpret_cast<const uint4*>(X + (size_t)c0 * AP);
        const uint4* x1 = reinterpret_cast<const uint4*>(X + (size_t)c1 * AP);
        uint4 t0 = x0[lane];
        uint4 t1 = x1[lane];
        fma8(a, t0, v0);
        fma8(a, t1, v1);
        if (lo8) {
            uint4 s0 = x0[32 + lane];
            uint4 s1 = x1[32 + lane];
            fma8(b, s0, v0);
            fma8(b, s1, v1);
        }
    }
    if (j < e) {
        int c = g_scol[j];
        float v = g_sval[j];
        const uint4* x4 = reinterpret_cast<const uint4*>(X + (size_t)c * AP);
        fma8(a, x4[lane], v);
        if (lo8) fma8(b, x4[32 + lane], v);
    }
}

__device__ __forceinline__ void spmm_store_lin(__half* __restrict__ O, int orow,
                                               int lane, bool lo8,
                                               const float* a, const float* b) {
    __half2 h0 = __floats2half2_rn(a[0], a[1]);
    __half2 h1 = __floats2half2_rn(a[2], a[3]);
    __half2 h2 = __floats2half2_rn(a[4], a[5]);
    __half2 h3 = __floats2half2_rn(a[6], a[7]);
    uint4 pk;
    pk.x = *reinterpret_cast<uint32_t*>(&h0);
    pk.y = *reinterpret_cast<uint32_t*>(&h1);
    pk.z = *reinterpret_cast<uint32_t*>(&h2);
    pk.w = *reinterpret_cast<uint32_t*>(&h3);
    __stcs(reinterpret_cast<uint4*>(O + (size_t)orow * AP) + lane, pk);
    if (lo8) {
        h0 = __floats2half2_rn(b[0], b[1]);
        h1 = __floats2half2_rn(b[2], b[3]);
        h2 = __floats2half2_rn(b[4], b[5]);
        h3 = __floats2half2_rn(b[6], b[7]);
        pk.x = *reinterpret_cast<uint32_t*>(&h0);
        pk.y = *reinterpret_cast<uint32_t*>(&h1);
        pk.z = *reinterpret_cast<uint32_t*>(&h2);
        pk.w = *reinterpret_cast<uint32_t*>(&h3);
        __stcs(reinterpret_cast<uint4*>(O + (size_t)orow * AP) + 32 + lane, pk);
    }
}

__global__ void spmm_sc_kernel(const __half* __restrict__ X, __half* __restrict__ O,
                               const int* __restrict__ rowlist,
                               const int* __restrict__ pcount) {
    int widx = (blockIdx.x * blockDim.x + threadIdx.x) >> 5;
    int lane = threadIdx.x & 31;
    int cnt = *pcount;
    if (widx >= cnt) return;
    int row = rowlist[widx];
    bool lo8 = lane < 8;
    float a[8] = {0,0,0,0,0,0,0,0};
    float b[8] = {0,0,0,0,0,0,0,0};
    spmm_accum(X, row, lane, lo8, a, b);
    spmm_store_lin(O, row, lane, lo8, a, b);
}

__global__ void spmm_dn_kernel(const __half* __restrict__ X, __half* __restrict__ O,
                               const int* __restrict__ node) {
    int b = (blockIdx.x * blockDim.x + threadIdx.x) >> 5;
    int lane = threadIdx.x & 31;
    if (b >= BATCH) return;
    int row = node[b];
    bool lo8 = lane < 8;
    float a[8] = {0,0,0,0,0,0,0,0};
    float bb[8] = {0,0,0,0,0,0,0,0};
    spmm_accum(X, row, lane, lo8, a, bb);
    spmm_store_lin(O, b, lane, lo8, a, bb);
}

// ================= host launch =================
extern "C" void kernel_launch(void* const* d_in, const int* in_sizes, int n_in,
                              void* d_out, int out_size) {
    const float* input = (const float*)d_in[0];
    const int*   node  = (const int*)d_in[1];
    const int*   erow  = (const int*)d_in[2];
    const int*   ecol  = (const int*)d_in[3];
    const float* H0    = (const float*)d_in[4];
    const float* W1    = (const float*)d_in[5];
    const float* W2    = (const float*)d_in[6];
    const float* Wa    = (const float*)d_in[7];
    const float* ba    = (const float*)d_in[8];
    const float* Wb    = (const float*)d_in[9];
    const float* bb    = (const float*)d_in[10];
    const float* Wc    = (const float*)d_in[11];
    const float* bc    = (const float*)d_in[12];
    float*       out   = (float*)d_out;

    void *p_act, *p_x16, *p_w1t, *p_w2t, *p_fcf16, *p_wat, *p_wbt, *p_h1f16;
    void *p_list1, *p_list3, *p_n1, *p_n3;
    cudaGetSymbolAddress(&p_act,    g_act);
    cudaGetSymbolAddress(&p_x16,    g_x16);
    cudaGetSymbolAddress(&p_w1t,    g_w1t);
    cudaGetSymbolAddress(&p_w2t,    g_w2t);
    cudaGetSymbolAddress(&p_fcf16,  g_fcf16);
    cudaGetSymbolAddress(&p_wat,    g_wat);
    cudaGetSymbolAddress(&p_wbt,    g_wbt);
    cudaGetSymbolAddress(&p_h1f16,  g_h1f16);
    cudaGetSymbolAddress(&p_list1,  g_list1);
    cudaGetSymbolAddress(&p_list3,  g_list3);
    cudaGetSymbolAddress(&p_n1,     g_n1);
    cudaGetSymbolAddress(&p_n3,     g_n3);

    cudaFuncSetAttribute(gemm_f16_kernel,
                         cudaFuncAttributeMaxDynamicSharedMemorySize, GS_TOTAL);

    static cudaStream_t s2 = nullptr, s3 = nullptr;
    static cudaEvent_t evF = nullptr, evAct = nullptr, evCsr = nullptr;
    if (!s2) {
        cudaStreamCreateWithFlags(&s2, cudaStreamNonBlocking);
        cudaStreamCreateWithFlags(&s3, cudaStreamNonBlocking);
        cudaEventCreateWithFlags(&evF, cudaEventDisableTiming);
        cudaEventCreateWithFlags(&evAct, cudaEventDisableTiming);
        cudaEventCreateWithFlags(&evCsr, cudaEventDisableTiming);
    }

    const int TPB = 256;
    const int nvBlocks = (NV + TPB - 1) / TPB;
    const int ne4Blocks = (NE / 4 + TPB - 1) / TPB;
    const int nv4Blocks = (NV / 4 + TPB - 1) / TPB;

    cudaEventRecord(evF, 0);

    // ---- s2: frontier construction + pre_act ----
    cudaStreamWaitEvent(s2, evF, 0);
    mark_node_kernel<<<(BATCH + TPB - 1) / TPB, TPB, 0, s2>>>(node);
    mark_1hop_kernel<<<ne4Blocks, TPB, 0, s2>>>(erow, ecol);
    mark_2hop_kernel<<<ne4Blocks, TPB, 0, s2>>>(erow, ecol);
    compact_both_kernel<<<nv4Blocks, TPB, 0, s2>>>();
    pre_act_list_kernel<<<(NV * 75 + TPB - 1) / TPB, TPB, 0, s2>>>(
        H0, (int*)p_list3, (int*)p_n3);
    cudaEventRecord(evAct, s2);

    // ---- s3: shortened CSR build ----
    cudaStreamWaitEvent(s3, evF, 0);
    zero_both_kernel<<<nvBlocks, TPB, 0, s3>>>();
    count_kernel<<<ne4Blocks, TPB, 0, s3>>>(erow);
    scanA_kernel<<<NBLK_SCAN, 1024, 0, s3>>>();
    scanB_kernel<<<1, 128, 0, s3>>>();
    scanC_kernel<<<nvBlocks, TPB, 0, s3>>>();
    scatter_kernel<<<ne4Blocks, TPB, 0, s3>>>(erow, ecol);
    cudaEventRecord(evCsr, s3);

    // ---- main stream: weight + input conversions + out init ----
    pre_wT_kernel<<<(EMB * EMB + TPB - 1) / TPB, TPB>>>(W1, EMB, EMB, AP, (__half*)p_w1t);
    pre_wT_kernel<<<(EMB * EMB + TPB - 1) / TPB, TPB>>>(W2, EMB, EMB, AP, (__half*)p_w2t);
    pre_wT_kernel<<<(FCK * HID + TPB - 1) / TPB, TPB>>>(Wa, FCK, HID, FCP, (__half*)p_wat);
    pre_wT_kernel<<<(HID * HID + TPB - 1) / TPB, TPB>>>(Wb, HID, HID, HP, (__half*)p_wbt);
    pre_input_f16_kernel<<<(BATCH * 192 + TPB - 1) / TPB, TPB>>>(input);
    init_out_kernel<<<(BATCH * 2 + TPB - 1) / TPB, TPB>>>(out, bc);

    // ---- join act + CSR, then Y = A*H0 on S1 rows (linear, fp16) ----
    cudaStreamWaitEvent(0, evAct, 0);
    cudaStreamWaitEvent(0, evCsr, 0);
    int spmmBlocks = (NV * 32 + TPB - 1) / TPB;
    spmm_sc_kernel<<<spmmBlocks, TPB>>>((__half*)p_act, (__half*)p_x16,
                                        (int*)p_list1, (int*)p_n1);

    // ---- H1 = sigmoid(Y @ W1) on S1 rows ----
    dim3 gbig(2, (NV + 127) / 128);
    gemm_f16_kernel<<<gbig, 512, GS_TOTAL>>>(
        (__half*)p_x16, AP, (__half*)p_w1t, AP,
        nullptr, 0, (__half*)p_act, AP, nullptr,
        (int*)p_list1, (int*)p_n1, nullptr, nullptr, NV, EMB, AP, 2);

    // ---- Z = A*H1 at node rows, densely packed ----
    spmm_dn_kernel<<<(BATCH * 32 + TPB - 1) / TPB, TPB>>>(
        (__half*)p_act, (__half*)p_x16, node);

    // ---- fc[:, 0:300] = sigmoid(Z @ W2) ----
    dim3 g2(2, BATCH / 128);
    gemm_f16_kernel<<<g2, 512, GS_TOTAL>>>(
        (__half*)p_x16, AP, (__half*)p_w2t, AP,
        nullptr, 0, (__half*)p_fcf16, FCP, nullptr,
        nullptr, nullptr, nullptr, nullptr, BATCH, EMB, AP, 2);

    // ---- MLP-G1: h1 = sigmoid(fc @ Wa + ba) ----
    dim3 gmlp(4, BATCH / 128);
    gemm_f16_kernel<<<gmlp, 512, GS_TOTAL>>>(
        (__half*)p_fcf16, FCP, (__half*)p_wat, FCP,
        nullptr, 0, (__half*)p_h1f16, HP, ba,
        nullptr, nullptr, nullptr, nullptr, BATCH, HID, FCP, 2);

    // ---- MLP-G2 with fused final: out += sigmoid(h1@Wb + bb) @ Wc ----
    gemm_f16_kernel<<<gmlp, 512, GS_TOTAL>>>(
        (__half*)p_h1f16, HP, (__half*)p_wbt, HP,
        nullptr, 0, nullptr, 0, bb,
        nullptr, nullptr, Wc, out, BATCH, HID, HP, 5);
}